// round 15
// baseline (speedup 1.0000x reference)
#include <cuda_runtime.h>
#include <cstdint>

// ---------------- problem constants ----------------
#define BATCH   16
#define HH      56
#define WW      56
#define NPIX    (HH*WW)        // 3136
#define C       384
#define HEADS   8
#define HD      48
#define SRR     2
#define PH      (HH/SRR)       // 28
#define PW      (WW/SRR)       // 28
#define NP      (PH*PW)        // 784
#define BH      (BATCH*HEADS)  // 128
#define SCALE   0.14433756729740643f  // 48^-0.5
#define LOG2E   1.4426950408889634f
#define EPS     1e-5f

// ---------------- scratch ----------------
__device__ float g_q[(size_t)BH * NP * HD];               // tf32(SCALE*LOG2E*q)
__device__ float g_k[(size_t)BH * NP * HD];               // tf32(k)
__device__ float g_vt[(size_t)BH * HD * NP];              // tf32(v), transposed [bh][d][key]
__device__ float g_o[(size_t)BATCH * NP * C];
__device__ float g_y[(size_t)BATCH * NPIX * C];
__device__ float g_xp[(size_t)BATCH * NP * C];            // pooled, tf32-rounded x
__device__ float g_wq[(size_t)3 * C * C];                 // tf32-rounded qkv_w
__device__ float g_wp[(size_t)C * C];                     // tf32-rounded proj_w

// ---------------- tf32 helpers ----------------
__device__ __forceinline__ uint32_t f2tf(float f) {
    uint32_t u;
    asm("cvt.rna.tf32.f32 %0, %1;" : "=r"(u) : "f"(f));
    return u;
}
__device__ __forceinline__ float f2tf_f(float f) {
    return __uint_as_float(f2tf(f));
}
__device__ __forceinline__ float ex2f(float x) {
    float y;
    asm("ex2.approx.f32 %0, %1;" : "=f"(y) : "f"(x));
    return y;
}

__device__ __forceinline__ void mma_tf32(float* d, const uint32_t* a, const uint32_t* b) {
    asm volatile(
        "mma.sync.aligned.m16n8k8.row.col.f32.tf32.tf32.f32 "
        "{%0,%1,%2,%3}, {%4,%5,%6,%7}, {%8,%9}, {%0,%1,%2,%3};\n"
        : "+f"(d[0]), "+f"(d[1]), "+f"(d[2]), "+f"(d[3])
        : "r"(a[0]), "r"(a[1]), "r"(a[2]), "r"(a[3]),
          "r"(b[0]), "r"(b[1]));
}

__device__ __forceinline__ void cp16(uint32_t* smem_dst, const float* gsrc) {
    uint32_t s = (uint32_t)__cvta_generic_to_shared(smem_dst);
    asm volatile("cp.async.ca.shared.global [%0], [%1], 16;\n" :: "r"(s), "l"(gsrc));
}

// =====================================================================
// Kernel 0: prep — gather pooled x (rounded), round weights.
// =====================================================================
#define PREP_N1 (BATCH*NP*(C/4))
#define PREP_N2 (3*C*(C/4))
#define PREP_N3 (C*(C/4))
__global__ __launch_bounds__(256) void prep_kernel(
    const float* __restrict__ x, const float* __restrict__ qkv_w,
    const float* __restrict__ proj_w)
{
    const int idx = blockIdx.x * 256 + threadIdx.x;
    if (idx < PREP_N1) {
        const int m  = idx / (C/4);
        const int k  = (idx - m * (C/4)) * 4;
        const int b  = m / NP;
        const int i  = m - b * NP;
        const int hi = (i / PW) * SRR;
        const int wi = (i - (i / PW) * PW) * SRR;
        float4 v = *(const float4*)(x + ((size_t)b * NPIX + hi * WW + wi) * C + k);
        v.x = f2tf_f(v.x); v.y = f2tf_f(v.y); v.z = f2tf_f(v.z); v.w = f2tf_f(v.w);
        *(float4*)(g_xp + (size_t)m * C + k) = v;
    } else if (idx < PREP_N1 + PREP_N2) {
        const int e = (idx - PREP_N1) * 4;
        float4 v = *(const float4*)(qkv_w + e);
        v.x = f2tf_f(v.x); v.y = f2tf_f(v.y); v.z = f2tf_f(v.z); v.w = f2tf_f(v.w);
        *(float4*)(g_wq + e) = v;
    } else if (idx < PREP_N1 + PREP_N2 + PREP_N3) {
        const int e = (idx - PREP_N1 - PREP_N2) * 4;
        float4 v = *(const float4*)(proj_w + e);
        v.x = f2tf_f(v.x); v.y = f2tf_f(v.y); v.z = f2tf_f(v.z); v.w = f2tf_f(v.w);
        *(float4*)(g_wp + e) = v;
    }
}

// =====================================================================
// Shared GEMM mainloop: 128x128 block tile, BK=32, 256 threads,
// 8 warps (4x2), 32x64 warp tile, 3-stage cp.async pipeline.
// SINGLE sync per stage: wait_group -> __syncthreads -> issue it+2 ->
// compute.  (Buffer (it+2)%3 == (it-1)%3 was consumed at it-1; every
// warp past the sync has finished that compute, so overwrite is safe.)
// XOR-swizzled smem at exact stride 32.
// =====================================================================
#define GSW 32
#define STG (128*GSW)     // words per stage
#define NIT (C/32)        // 12 k-iterations

__device__ __forceinline__ void gemm_mainloop(
    const float* __restrict__ Arows, const float* __restrict__ Brows,
    uint32_t* As, uint32_t* Bs,
    float acc[2][8][4],
    int warp_m, int warp_n, int gid, int t4, int tid)
{
    const int rbase = tid >> 3;                   // 0..31
    const int cw    = (tid & 7) * 4;              // logical chunk word
    const int scw   = cw ^ ((rbase & 3) << 3);    // swizzled (row&3 const over t)
    const int xorw  = (gid & 3) << 3;             // frag-read swizzle term

    auto load_stage = [&](int it, int stage) {
        uint32_t* Ad = As + stage * STG;
        uint32_t* Bd = Bs + stage * STG;
        const int k0 = it * 32;
        #pragma unroll
        for (int t = 0; t < 4; t++) {
            const int r = rbase + t * 32;
            cp16(Ad + r * GSW + scw, Arows + (size_t)r * C + k0 + cw);
            cp16(Bd + r * GSW + scw, Brows + (size_t)r * C + k0 + cw);
        }
        asm volatile("cp.async.commit_group;\n");
    };

    load_stage(0, 0);
    load_stage(1, 1);

    int cbuf = 0, lbuf = 2;
    #pragma unroll 1
    for (int it = 0; it < NIT; it++) {
        // pending groups here: {it} and (if it+1<NIT) {it+1}
        if (it + 1 < NIT) {
            asm volatile("cp.async.wait_group 1;\n");
        } else {
            asm volatile("cp.async.wait_group 0;\n");
        }
        __syncthreads();

        if (it + 2 < NIT) {
            load_stage(it + 2, lbuf);
            if (++lbuf == 3) lbuf = 0;
        }

        const uint32_t* Ac = As + cbuf * STG;
        const uint32_t* Bc = Bs + cbuf * STG;
        #pragma unroll
        for (int ks = 0; ks < 32; ks += 8) {
            const int col = (ks ^ xorw) + 2 * t4;
            uint32_t af[2][4], bf[8][2];
            #pragma unroll
            for (int i = 0; i < 2; i++) {
                const int r0 = warp_m + i * 16 + gid;
                const uint2 p0 = *(const uint2*)&Ac[r0 * GSW + col];
                const uint2 p1 = *(const uint2*)&Ac[(r0 + 8) * GSW + col];
                af[i][0] = p0.x; af[i][1] = p1.x; af[i][2] = p0.y; af[i][3] = p1.y;
            }
            #pragma unroll
            for (int j = 0; j < 8; j++) {
                const int cc = warp_n + j * 8 + gid;
                const uint2 bb = *(const uint2*)&Bc[cc * GSW + col];
                bf[j][0] = bb.x; bf[j][1] = bb.y;
            }
            #pragma unroll
            for (int i = 0; i < 2; i++)
                #pragma unroll
                for (int j = 0; j < 8; j++)
                    mma_tf32(acc[i][j], af[i], bf[j]);
        }
        if (++cbuf == 3) cbuf = 0;
    }
}

// =====================================================================
// Kernel 1: QKV GEMM.  Epilogue pre-rounds q (scaled by SCALE*LOG2E),
// k, and writes V transposed+rounded for the attention kernel.
// =====================================================================
__global__ __launch_bounds__(256, 2) void qkv_gemm_tf32(const float* __restrict__ bias)
{
    __shared__ uint32_t As[3 * STG];
    __shared__ uint32_t Bs[3 * STG];

    const int tile_m = blockIdx.y * 128;
    const int tile_n = blockIdx.x * 128;
    const int tid  = threadIdx.x;
    const int wid  = tid >> 5;
    const int lane = tid & 31;
    const int gid  = lane >> 2;
    const int t4   = lane & 3;
    const int warp_m = (wid & 3) * 32;
    const int warp_n = (wid >> 2) * 64;

    float acc[2][8][4] = {};
    gemm_mainloop(g_xp + (size_t)tile_m * C, g_wq + (size_t)tile_n * C,
                  As, Bs, acc, warp_m, warp_n, gid, t4, tid);

    #pragma unroll
    for (int i = 0; i < 2; i++) {
        #pragma unroll
        for (int half = 0; half < 2; half++) {
            const int gm = tile_m + warp_m + i * 16 + gid + half * 8;
            const int ob = gm / NP;
            const int oi = gm - ob * NP;
            #pragma unroll
            for (int j = 0; j < 8; j++) {
                #pragma unroll
                for (int e = 0; e < 2; e++) {
                    const int gj = tile_n + warp_n + j * 8 + 2 * t4 + e;
                    const float val = acc[i][j][half * 2 + e] + bias[gj];
                    const int which = gj / C;
                    const int c2    = gj - which * C;
                    const int head  = c2 / HD;
                    const int d     = c2 - head * HD;
                    const int bhid  = ob * HEADS + head;
                    if (which == 0)
                        g_q[((size_t)bhid * NP + oi) * HD + d] = f2tf_f(SCALE * LOG2E * val);
                    else if (which == 1)
                        g_k[((size_t)bhid * NP + oi) * HD + d] = f2tf_f(val);
                    else
                        g_vt[((size_t)bhid * HD + d) * NP + oi] = f2tf_f(val);
                }
            }
        }
    }
}

// =====================================================================
// Kernel 4: proj GEMM.
// =====================================================================
__global__ __launch_bounds__(256, 2) void proj_gemm_tf32(
    const float* __restrict__ bias, float* __restrict__ out)
{
    __shared__ uint32_t As[3 * STG];
    __shared__ uint32_t Bs[3 * STG];

    const int tile_m = blockIdx.y * 128;
    const int tile_n = blockIdx.x * 128;
    const int tid  = threadIdx.x;
    const int wid  = tid >> 5;
    const int lane = tid & 31;
    const int gid  = lane >> 2;
    const int t4   = lane & 3;
    const int warp_m = (wid & 3) * 32;
    const int warp_n = (wid >> 2) * 64;

    float acc[2][8][4] = {};
    gemm_mainloop(g_y + (size_t)tile_m * C, g_wp + (size_t)tile_n * C,
                  As, Bs, acc, warp_m, warp_n, gid, t4, tid);

    #pragma unroll
    for (int i = 0; i < 2; i++) {
        #pragma unroll
        for (int half = 0; half < 2; half++) {
            const int gm = tile_m + warp_m + i * 16 + gid + half * 8;
            #pragma unroll
            for (int j = 0; j < 8; j++) {
                const int gj = tile_n + warp_n + j * 8 + 2 * t4;
                float2 v;
                v.x = acc[i][j][half * 2 + 0] + bias[gj];
                v.y = acc[i][j][half * 2 + 1] + bias[gj + 1];
                *(float2*)(out + (size_t)gm * C + gj) = v;
            }
        }
    }
}

// =====================================================================
// Kernel 2: flash attention, tf32 mma, cp.async double-buffered KV.
// Single sync per tile: wait_group 0 -> __syncthreads -> issue kt+1 ->
// compute.  (Next load overwrites the buffer consumed at kt-1, done by
// all warps once they pass the sync.)
// - q pre-scaled by SCALE*LOG2E -> bare ex2.approx for exp.
// - l via tensor core (Vst row 48 = ones), no online max.
// - Even/odd k-permutation, D-frag layout HW-fixed.
// =====================================================================
#define QB 112
#define KB 56
#define ATHREADS 224
#define KSTRIDE 56
#define VSTRIDE 56
#define VROWS 56          // 48 data rows + ones row (48) + 7 zero rows

__global__ __launch_bounds__(ATHREADS, 2) void attn_mma(float* __restrict__ o_out)
{
    __shared__ uint32_t Ks[2][KB][KSTRIDE];
    __shared__ uint32_t Vst[2][VROWS][VSTRIDE];

    const int bh = blockIdx.y;
    const int qbase = blockIdx.x * QB;
    const int tid  = threadIdx.x;
    const int w    = tid >> 5;
    const int lane = tid & 31;
    const int gid  = lane >> 2;
    const int t4   = lane & 3;

    const float* kbp = g_k  + (size_t)bh * NP * HD;
    const float* vtp = g_vt + (size_t)bh * HD * NP;

    // static rows 48..55 of both V buffers: row 48 = 1.0, rest = 0
    for (int idx = tid; idx < 8 * VSTRIDE; idx += ATHREADS) {
        const int r = 48 + idx / VSTRIDE;
        const int c = idx - (idx / VSTRIDE) * VSTRIDE;
        const uint32_t v = (r == 48) ? 0x3f800000u : 0u;
        Vst[0][r][c] = v;
        Vst[1][r][c] = v;
    }

    // Q fragments, permuted-k slots (2t4, 2t4+1); already scaled + rounded
    uint32_t qa[6][4];
    {
        const uint32_t* q0 = (const uint32_t*)g_q + ((size_t)bh * NP + qbase + w * 16 + gid) * HD;
        const uint32_t* q1 = q0 + 8 * HD;
        #pragma unroll
        for (int ks = 0; ks < 6; ks++) {
            const uint2 p0 = *(const uint2*)(q0 + ks * 8 + 2 * t4);
            const uint2 p1 = *(const uint2*)(q1 + ks * 8 + 2 * t4);
            qa[ks][0] = p0.x; qa[ks][1] = p1.x; qa[ks][2] = p0.y; qa[ks][3] = p1.y;
        }
    }

    // precomputed per-thread load addresses (3 K chunks + 3 V chunks)
    const float* kg[3]; const float* vg[3];
    int koff[3], voff[3];
    #pragma unroll
    for (int r = 0; r < 3; r++) {
        const int idx = tid + r * ATHREADS;
        const int krow = idx / 12, kc = (idx - krow * 12) * 4;
        const int vrow = idx / 14, vc = (idx - vrow * 14) * 4;
        kg[r]   = kbp + (size_t)krow * HD + kc;
        vg[r]   = vtp + (size_t)vrow * NP + vc;
        koff[r] = krow * KSTRIDE + kc;
        voff[r] = vrow * VSTRIDE + vc;
    }

    auto load_tile = [&](int kt, int bufi) {
        uint32_t* kd = &Ks[bufi][0][0];
        uint32_t* vd = &Vst[bufi][0][0];
        #pragma unroll
        for (int r = 0; r < 3; r++)
            cp16(kd + koff[r], kg[r] + (size_t)kt * KB * HD);
        #pragma unroll
        for (int r = 0; r < 3; r++)
            cp16(vd + voff[r], vg[r] + kt * KB);
        asm volatile("cp.async.commit_group;\n");
    };

    float oacc[7][4] = {};   // [0..5] = O columns, [6] = l (col 48)

    load_tile(0, 0);
    int buf = 0;

    #pragma unroll 1
    for (int kt = 0; kt < NP / KB; kt++) {
        // only group kt is pending here (kt+1 not yet issued)
        asm volatile("cp.async.wait_group 0;\n");
        __syncthreads();

        if (kt + 1 < NP / KB)
            load_tile(kt + 1, buf ^ 1);

        // S' = (log2e-scaled Q) @ K^T
        float s[7][4] = {};
        #pragma unroll
        for (int j = 0; j < 7; j++) {
            #pragma unroll
            for (int ks = 0; ks < 6; ks++) {
                const uint2 bb = *(const uint2*)&Ks[buf][j * 8 + gid][ks * 8 + 2 * t4];
                uint32_t bfr[2] = { bb.x, bb.y };
                mma_tf32(s[j], qa[ks], bfr);
            }
        }

        // P = exp2(S')
        #pragma unroll
        for (int j = 0; j < 7; j++) {
            s[j][0] = ex2f(s[j][0]); s[j][1] = ex2f(s[j][1]);
            s[j][2] = ex2f(s[j][2]); s[j][3] = ex2f(s[j][3]);
        }

        // O += P @ V (n=0..5) and l += P @ ones (n=6)
        #pragma unroll
        for (int j = 0; j < 7; j++) {
            uint32_t a[4];
            a[0] = f2tf(s[j][0]); a[1] = f2tf(s[j][2]);
            a[2] = f2tf(s[j][1]); a[3] = f2tf(s[j][3]);
            #pragma unroll
            for (int n = 0; n < 7; n++) {
                const uint2 bb = *(const uint2*)&Vst[buf][n * 8 + gid][j * 8 + 2 * t4];
                uint32_t bfr[2] = { bb.x, bb.y };
                mma_tf32(oacc[n], a, bfr);
            }
        }
        buf ^= 1;
    }

    // l sits in col 48 -> t4==0 lane of each quad; broadcast within quad
    const int lsrc = lane & ~3;
    const float l0 = __shfl_sync(0xffffffffu, oacc[6][0], lsrc);
    const float l1 = __shfl_sync(0xffffffffu, oacc[6][2], lsrc);

    const int b = bh >> 3, head = bh & 7;
    const int q0r = qbase + w * 16 + gid;
    const float inv0 = 1.f / l0;
    const float inv1 = 1.f / l1;
    float* od0 = o_out + ((size_t)b * NP + q0r) * C + head * HD;
    float* od1 = od0 + (size_t)8 * C;
    #pragma unroll
    for (int n = 0; n < 6; n++) {
        const int col = n * 8 + 2 * t4;
        float2 r0; r0.x = oacc[n][0] * inv0; r0.y = oacc[n][1] * inv0;
        float2 r1; r1.x = oacc[n][2] * inv1; r1.y = oacc[n][3] * inv1;
        *(float2*)(od0 + col) = r0;
        *(float2*)(od1 + col) = r1;
    }
}

// =====================================================================
// Kernel 3: upsample + bias + LN, 2x2 quad per block.
// =====================================================================
__global__ __launch_bounds__(128) void up_ln_kernel(
    const float* __restrict__ lp_w, const float* __restrict__ lp_b,
    const float* __restrict__ ln_w, const float* __restrict__ ln_b)
{
    const int pp0 = blockIdx.x;
    const int b   = pp0 / NP;
    const int p2  = pp0 - b * NP;
    const int hh  = p2 / PW;
    const int ww  = p2 - hh * PW;
    const float* orow = g_o + (size_t)pp0 * C;

    const int tid = threadIdx.x;
    float ov[3], lb[3], lw[3], lnbv[3];
    float4 w4[3];
    #pragma unroll
    for (int r = 0; r < 3; r++) {
        const int c = tid + r * 128;
        ov[r] = orow[c];
        w4[r] = *(const float4*)(lp_w + c * 4);
        lb[r] = lp_b[c];
        lw[r] = ln_w[c];
        lnbv[r] = ln_b[c];
    }

    float s[4] = {}, s2[4] = {};
    #pragma unroll
    for (int r = 0; r < 3; r++) {
        const float v0 = ov[r] * w4[r].x + lb[r];
        const float v1 = ov[r] * w4[r].y + lb[r];
        const float v2 = ov[r] * w4[r].z + lb[r];
        const float v3 = ov[r] * w4[r].w + lb[r];
        s[0] += v0; s2[0] += v0 * v0;
        s[1] += v1; s2[1] += v1 * v1;
        s[2] += v2; s2[2] += v2 * v2;
        s[3] += v3; s2[3] += v3 * v3;
    }

    __shared__ float rs[4][4], rs2[4][4];
    #pragma unroll
    for (int pq = 0; pq < 4; pq++) {
        float a = s[pq], a2 = s2[pq];
        #pragma unroll
        for (int off = 16; off > 0; off >>= 1) {
            a  += __shfl_down_sync(0xffffffffu, a,  off);
            a2 += __shfl_down_sync(0xffffffffu, a2, off);
        }
        if ((tid & 31) == 0) { rs[tid >> 5][pq] = a; rs2[tid >> 5][pq] = a2; }
    }
    __syncthreads();

    float mean[4], inv[4];
    #pragma unroll
    for (int pq = 0; pq < 4; pq++) {
        const float S  = rs[0][pq] + rs[1][pq] + rs[2][pq] + rs[3][pq];
        const float S2 = rs2[0][pq] + rs2[1][pq] + rs2[2][pq] + rs2[3][pq];
        mean[pq] = S * (1.f / C);
        const float var = S2 * (1.f / C) - mean[pq] * mean[pq];
        inv[pq] = rsqrtf(var + EPS);
    }

    #pragma unroll
    for (int pq = 0; pq < 4; pq++) {
        const int pp = pq >> 1, qq = pq & 1;
        float* yrow = g_y + ((size_t)b * NPIX + (2 * hh + pp) * WW + (2 * ww + qq)) * C;
        #pragma unroll
        for (int r = 0; r < 3; r++) {
            const int c = tid + r * 128;
            const float wsel = (pq == 0) ? w4[r].x : (pq == 1) ? w4[r].y
                              : (pq == 2) ? w4[r].z : w4[r].w;
            const float val = ov[r] * wsel + lb[r];
            yrow[c] = f2tf_f((val - mean[pq]) * inv[pq] * lw[r] + lnbv[r]);
        }
    }
}

// =====================================================================
// launcher
// =====================================================================
extern "C" void kernel_launch(void* const* d_in, const int* in_sizes, int n_in,
                              void* d_out, int out_size)
{
    const float* x      = (const float*)d_in[0];
    const float* qkv_w  = (const float*)d_in[1];
    const float* qkv_b  = (const float*)d_in[2];
    const float* proj_w = (const float*)d_in[3];
    const float* proj_b = (const float*)d_in[4];
    const float* lp_w   = (const float*)d_in[5];
    const float* lp_b   = (const float*)d_in[6];
    const float* ln_w   = (const float*)d_in[7];
    const float* ln_b   = (const float*)d_in[8];
    float* out = (float*)d_out;

    float* o_ptr = nullptr;
    cudaGetSymbolAddress((void**)&o_ptr, g_o);

    // 0) prep
    {
        const int total = PREP_N1 + PREP_N2 + PREP_N3;
        prep_kernel<<<(total + 255) / 256, 256>>>(x, qkv_w, proj_w);
    }
    // 1) QKV gemm
    {
        dim3 grid((3 * C) / 128, (BATCH * NP) / 128);
        qkv_gemm_tf32<<<grid, 256>>>(qkv_b);
    }
    // 2) attention
    {
        dim3 grid(NP / QB, BH);
        attn_mma<<<grid, ATHREADS>>>(o_ptr);
    }
    // 3) upsample + LN
    {
        up_ln_kernel<<<BATCH * NP, 128>>>(lp_w, lp_b, ln_w, ln_b);
    }
    // 4) proj gemm
    {
        dim3 grid(C / 128, (BATCH * NPIX) / 128);
        proj_gemm_tf32<<<grid, 256>>>(proj_b, out);
    }
}

// round 16
// speedup vs baseline: 1.4411x; 1.4411x over previous
#include <cuda_runtime.h>
#include <cuda_fp16.h>
#include <cstdint>

// ---------------- problem constants ----------------
#define BATCH   16
#define HH      56
#define WW      56
#define NPIX    (HH*WW)        // 3136
#define C       384
#define HEADS   8
#define HD      48
#define SRR     2
#define PH      (HH/SRR)       // 28
#define PW      (WW/SRR)       // 28
#define NP      (PH*PW)        // 784
#define BH      (BATCH*HEADS)  // 128
#define SCALE   0.14433756729740643f  // 48^-0.5
#define LOG2E   1.4426950408889634f
#define EPS     1e-5f

// ---------------- scratch (fp16 operands, PERM16 k-layout) ----------------
__device__ __half g_q [(size_t)BH * NP * HD];    // fp16(SCALE*LOG2E*q), d PERM16
__device__ __half g_k [(size_t)BH * NP * HD];    // fp16(k), d PERM16
__device__ __half g_vt[(size_t)BH * HD * NP];    // fp16(v) transposed [bh][d][key], key PERM16
__device__ float  g_o [(size_t)BATCH * NP * C];
__device__ __half g_y [(size_t)BATCH * NPIX * C];   // fp16, c PERM16
__device__ __half g_xp[(size_t)BATCH * NP * C];     // pooled x, fp16, c PERM16
__device__ __half g_wq[(size_t)3 * C * C];          // qkv_w fp16, c PERM16
__device__ __half g_wp[(size_t)C * C];              // proj_w fp16, c PERM16

// PERM16: within each 16-group, logical k -> physical pos so that one
// LDS.64 (4 fp16) at phys 4*t4 = logical {2t4, 2t4+1, 2t4+8, 2t4+9}.
__device__ __host__ __forceinline__ int perm16(int k) {
    return ((k & 7) >> 1) * 4 + ((k >> 3) << 1) + (k & 1);
}

__device__ __forceinline__ float ex2f(float x) {
    float y; asm("ex2.approx.f32 %0, %1;" : "=f"(y) : "f"(x)); return y;
}
__device__ __forceinline__ uint32_t packh2(float lo, float hi) {
    uint32_t r;
    asm("cvt.rn.f16x2.f32 %0, %1, %2;" : "=r"(r) : "f"(hi), "f"(lo));
    return r;
}

__device__ __forceinline__ void mma_f16(float* d, const uint32_t* a, const uint32_t* b) {
    asm volatile(
        "mma.sync.aligned.m16n8k16.row.col.f32.f16.f16.f32 "
        "{%0,%1,%2,%3}, {%4,%5,%6,%7}, {%8,%9}, {%0,%1,%2,%3};\n"
        : "+f"(d[0]), "+f"(d[1]), "+f"(d[2]), "+f"(d[3])
        : "r"(a[0]), "r"(a[1]), "r"(a[2]), "r"(a[3]),
          "r"(b[0]), "r"(b[1]));
}

__device__ __forceinline__ void cp16(uint32_t* smem_dst, const void* gsrc) {
    uint32_t s = (uint32_t)__cvta_generic_to_shared(smem_dst);
    asm volatile("cp.async.ca.shared.global [%0], [%1], 16;\n" :: "r"(s), "l"(gsrc));
}

// =====================================================================
// Kernel 0: prep — one 16-channel group per thread: gather pooled x,
// convert weights; all written fp16 in PERM16 order.
// =====================================================================
#define PG1 (BATCH*NP*(C/16))
#define PG2 (3*C*(C/16))
#define PG3 (C*(C/16))
__global__ __launch_bounds__(256) void prep_kernel(
    const float* __restrict__ x, const float* __restrict__ qkv_w,
    const float* __restrict__ proj_w)
{
    const int idx = blockIdx.x * 256 + threadIdx.x;
    const float* src;
    __half* dst;
    if (idx < PG1) {
        const int m = idx / (C/16), g = idx - m * (C/16);
        const int b = m / NP, i = m - b * NP;
        const int hi = (i / PW) * SRR;
        const int wi = (i - (i / PW) * PW) * SRR;
        src = x + ((size_t)b * NPIX + hi * WW + wi) * C + g * 16;
        dst = g_xp + (size_t)m * C + g * 16;
    } else if (idx < PG1 + PG2) {
        const int e = idx - PG1;
        const int row = e / (C/16), g = e - row * (C/16);
        src = qkv_w + (size_t)row * C + g * 16;
        dst = g_wq + (size_t)row * C + g * 16;
    } else if (idx < PG1 + PG2 + PG3) {
        const int e = idx - PG1 - PG2;
        const int row = e / (C/16), g = e - row * (C/16);
        src = proj_w + (size_t)row * C + g * 16;
        dst = g_wp + (size_t)row * C + g * 16;
    } else return;

    __half tmp[16];
    #pragma unroll
    for (int t = 0; t < 4; t++) {
        const float4 v = *(const float4*)(src + t * 4);
        tmp[perm16(4*t + 0)] = __float2half(v.x);
        tmp[perm16(4*t + 1)] = __float2half(v.y);
        tmp[perm16(4*t + 2)] = __float2half(v.z);
        tmp[perm16(4*t + 3)] = __float2half(v.w);
    }
    ((uint4*)dst)[0] = ((uint4*)tmp)[0];
    ((uint4*)dst)[1] = ((uint4*)tmp)[1];
}

// =====================================================================
// GEMM mainloop (fp16 m16n8k16): 128x128 block tile, BK=64 fp16
// (= 128B rows, same XOR swizzle as tf32 version), 256 threads,
// 8 warps (4x2), 32x64 warp tile, 3-stage cp.async, single sync/stage.
// =====================================================================
#define GSW 32              // words per smem row (64 fp16)
#define STG (128*GSW)
#define NIT (C/64)          // 6

__device__ __forceinline__ void gemm_mainloop(
    const __half* __restrict__ Arows, const __half* __restrict__ Brows,
    uint32_t* As, uint32_t* Bs,
    float acc[2][8][4],
    int warp_m, int warp_n, int gid, int t4, int tid)
{
    const int rbase = tid >> 3;                    // 0..31
    const int ch    = tid & 7;                     // 16B chunk (8 fp16)
    const int scw   = (ch * 4) ^ ((rbase & 3) << 3);
    const int xorw  = (gid & 3) << 3;

    auto load_stage = [&](int it, int stage) {
        uint32_t* Ad = As + stage * STG;
        uint32_t* Bd = Bs + stage * STG;
        const int k0 = it * 64;                    // fp16 units
        #pragma unroll
        for (int t = 0; t < 4; t++) {
            const int r = rbase + t * 32;
            cp16(Ad + r * GSW + scw, Arows + (size_t)r * C + k0 + ch * 8);
            cp16(Bd + r * GSW + scw, Brows + (size_t)r * C + k0 + ch * 8);
        }
        asm volatile("cp.async.commit_group;\n");
    };

    load_stage(0, 0);
    load_stage(1, 1);

    int cbuf = 0, lbuf = 2;
    #pragma unroll 1
    for (int it = 0; it < NIT; it++) {
        if (it + 1 < NIT) {
            asm volatile("cp.async.wait_group 1;\n");
        } else {
            asm volatile("cp.async.wait_group 0;\n");
        }
        __syncthreads();

        if (it + 2 < NIT) {
            load_stage(it + 2, lbuf);
            if (++lbuf == 3) lbuf = 0;
        }

        const uint32_t* Ac = As + cbuf * STG;
        const uint32_t* Bc = Bs + cbuf * STG;
        #pragma unroll
        for (int ks = 0; ks < 4; ks++) {           // 4 k16 windows per BK64
            const int col = ((ks * 8) ^ xorw) + 2 * t4;
            uint32_t af[2][4], bf[8][2];
            #pragma unroll
            for (int i = 0; i < 2; i++) {
                const int r0 = warp_m + i * 16 + gid;
                const uint2 p0 = *(const uint2*)&Ac[r0 * GSW + col];
                const uint2 p1 = *(const uint2*)&Ac[(r0 + 8) * GSW + col];
                af[i][0] = p0.x; af[i][1] = p1.x; af[i][2] = p0.y; af[i][3] = p1.y;
            }
            #pragma unroll
            for (int j = 0; j < 8; j++) {
                const int cc = warp_n + j * 8 + gid;
                const uint2 bb = *(const uint2*)&Bc[cc * GSW + col];
                bf[j][0] = bb.x; bf[j][1] = bb.y;
            }
            #pragma unroll
            for (int i = 0; i < 2; i++)
                #pragma unroll
                for (int j = 0; j < 8; j++)
                    mma_f16(acc[i][j], af[i], bf[j]);
        }
        if (++cbuf == 3) cbuf = 0;
    }
}

// =====================================================================
// Kernel 1: QKV GEMM.  Epilogue writes fp16 q (pre-scaled, d PERM16),
// k (d PERM16), V transposed (key PERM16).
// =====================================================================
__global__ __launch_bounds__(256, 2) void qkv_gemm_f16(const float* __restrict__ bias)
{
    __shared__ uint32_t As[3 * STG];
    __shared__ uint32_t Bs[3 * STG];

    const int tile_m = blockIdx.y * 128;
    const int tile_n = blockIdx.x * 128;
    const int tid  = threadIdx.x;
    const int wid  = tid >> 5;
    const int lane = tid & 31;
    const int gid  = lane >> 2;
    const int t4   = lane & 3;
    const int warp_m = (wid & 3) * 32;
    const int warp_n = (wid >> 2) * 64;

    float acc[2][8][4] = {};
    gemm_mainloop(g_xp + (size_t)tile_m * C, g_wq + (size_t)tile_n * C,
                  As, Bs, acc, warp_m, warp_n, gid, t4, tid);

    #pragma unroll
    for (int i = 0; i < 2; i++) {
        #pragma unroll
        for (int half = 0; half < 2; half++) {
            const int gm = tile_m + warp_m + i * 16 + gid + half * 8;
            const int ob = gm / NP;
            const int oi = gm - ob * NP;
            const int op = (oi & ~15) | perm16(oi & 15);   // key PERM16
            #pragma unroll
            for (int j = 0; j < 8; j++) {
                #pragma unroll
                for (int e = 0; e < 2; e++) {
                    const int gj = tile_n + warp_n + j * 8 + 2 * t4 + e;
                    const float val = acc[i][j][half * 2 + e] + bias[gj];
                    const int which = gj / C;
                    const int c2    = gj - which * C;
                    const int head  = c2 / HD;
                    const int d     = c2 - head * HD;
                    const int dp    = (d & ~15) | perm16(d & 15);
                    const int bhid  = ob * HEADS + head;
                    if (which == 0)
                        g_q[((size_t)bhid * NP + oi) * HD + dp] = __float2half(SCALE * LOG2E * val);
                    else if (which == 1)
                        g_k[((size_t)bhid * NP + oi) * HD + dp] = __float2half(val);
                    else
                        g_vt[((size_t)bhid * HD + d) * NP + op] = __float2half(val);
                }
            }
        }
    }
}

// =====================================================================
// Kernel 4: proj GEMM (fp16 operands, fp32 out).
// =====================================================================
__global__ __launch_bounds__(256, 2) void proj_gemm_f16(
    const float* __restrict__ bias, float* __restrict__ out)
{
    __shared__ uint32_t As[3 * STG];
    __shared__ uint32_t Bs[3 * STG];

    const int tile_m = blockIdx.y * 128;
    const int tile_n = blockIdx.x * 128;
    const int tid  = threadIdx.x;
    const int wid  = tid >> 5;
    const int lane = tid & 31;
    const int gid  = lane >> 2;
    const int t4   = lane & 3;
    const int warp_m = (wid & 3) * 32;
    const int warp_n = (wid >> 2) * 64;

    float acc[2][8][4] = {};
    gemm_mainloop(g_y + (size_t)tile_m * C, g_wp + (size_t)tile_n * C,
                  As, Bs, acc, warp_m, warp_n, gid, t4, tid);

    #pragma unroll
    for (int i = 0; i < 2; i++) {
        #pragma unroll
        for (int half = 0; half < 2; half++) {
            const int gm = tile_m + warp_m + i * 16 + gid + half * 8;
            #pragma unroll
            for (int j = 0; j < 8; j++) {
                const int gj = tile_n + warp_n + j * 8 + 2 * t4;
                float2 v;
                v.x = acc[i][j][half * 2 + 0] + bias[gj];
                v.y = acc[i][j][half * 2 + 1] + bias[gj + 1];
                *(float2*)(out + (size_t)gm * C + gj) = v;
            }
        }
    }
}

// =====================================================================
// Kernel 2: flash attention, fp16 m16n8k16.
// KB=112 keys/tile (7x16 -> PERM16-aligned), QB=112, 7 warps.
// S: 14 n-subtiles x 3 k16.  P packed to fp16 A-frags via cvt.f16x2.
// PV: 7 key-windows x 7 n-subtiles (6 O + ones-row l).
// No online max; single sync per tile; double-buffered cp.async.
// =====================================================================
#define QB 112
#define KB 112
#define ATH 224
#define KSTR 28      // words (48 fp16 data = 24w + pad)
#define VSTR 60      // words (112 fp16 keys = 56w + pad)
#define VROWS 56     // 48 d rows + ones row (48) + 7 zero rows
#define NTIL (NP/KB) // 7

__global__ __launch_bounds__(ATH, 2) void attn_mma(float* __restrict__ o_out)
{
    __shared__ uint32_t Ks[2][KB][KSTR];
    __shared__ uint32_t Vst[2][VROWS][VSTR];

    const int bh = blockIdx.y;
    const int qbase = blockIdx.x * QB;
    const int tid  = threadIdx.x;
    const int w    = tid >> 5;
    const int lane = tid & 31;
    const int gid  = lane >> 2;
    const int t4   = lane & 3;

    const __half* kbp = g_k  + (size_t)bh * NP * HD;
    const __half* vtp = g_vt + (size_t)bh * HD * NP;

    // static rows 48..55 of both V buffers: row 48 = 1.0h pairs, rest 0
    for (int idx = tid; idx < 8 * VSTR; idx += ATH) {
        const int r = 48 + idx / VSTR;
        const int c = idx - (idx / VSTR) * VSTR;
        const uint32_t v = (r == 48) ? 0x3c003c00u : 0u;
        Vst[0][r][c] = v;
        Vst[1][r][c] = v;
    }

    // Q fragments (pre-scaled, d PERM16): 3 k16 windows
    uint32_t qa[3][4];
    {
        const __half* q0 = g_q + ((size_t)bh * NP + qbase + w * 16 + gid) * HD;
        const __half* q1 = q0 + 8 * HD;
        #pragma unroll
        for (int ks = 0; ks < 3; ks++) {
            const uint2 p0 = *(const uint2*)(q0 + ks * 16 + 4 * t4);
            const uint2 p1 = *(const uint2*)(q1 + ks * 16 + 4 * t4);
            qa[ks][0] = p0.x; qa[ks][1] = p1.x; qa[ks][2] = p0.y; qa[ks][3] = p1.y;
        }
    }

    // per-thread tile-load addresses: K 112 rows x 6 chunks, V 48 rows x 14
    const __half* kg[3]; const __half* vg[3];
    int koff[3], voff[3];
    #pragma unroll
    for (int r = 0; r < 3; r++) {
        const int idx = tid + r * ATH;             // 0..671
        const int krow = idx / 6,  kc = (idx - krow * 6) * 8;
        const int vrow = idx / 14, vc = (idx - vrow * 14) * 8;
        kg[r]   = kbp + (size_t)krow * HD + kc;
        vg[r]   = vtp + (size_t)vrow * NP + vc;
        koff[r] = krow * KSTR + (idx - krow * 6) * 4;
        voff[r] = vrow * VSTR + (idx - vrow * 14) * 4;
    }

    auto load_tile = [&](int kt, int bufi) {
        uint32_t* kd = &Ks[bufi][0][0];
        uint32_t* vd = &Vst[bufi][0][0];
        #pragma unroll
        for (int r = 0; r < 3; r++)
            cp16(kd + koff[r], kg[r] + (size_t)kt * KB * HD);
        #pragma unroll
        for (int r = 0; r < 3; r++)
            cp16(vd + voff[r], vg[r] + kt * KB);
        asm volatile("cp.async.commit_group;\n");
    };

    float oacc[7][4] = {};   // [0..5] = O cols, [6] = l (col 48)

    load_tile(0, 0);
    int buf = 0;

    #pragma unroll 1
    for (int kt = 0; kt < NTIL; kt++) {
        asm volatile("cp.async.wait_group 0;\n");
        __syncthreads();

        if (kt + 1 < NTIL)
            load_tile(kt + 1, buf ^ 1);

        // S' = Qs @ K^T : 14 key-subtiles x 3 k16
        float s[14][4] = {};
        #pragma unroll
        for (int j = 0; j < 14; j++) {
            #pragma unroll
            for (int ks = 0; ks < 3; ks++) {
                const uint2 bb = *(const uint2*)&Ks[buf][j * 8 + gid][ks * 8 + 2 * t4];
                uint32_t bfr[2] = { bb.x, bb.y };
                mma_f16(s[j], qa[ks], bfr);
            }
        }

        // P = exp2(S')
        #pragma unroll
        for (int j = 0; j < 14; j++) {
            s[j][0] = ex2f(s[j][0]); s[j][1] = ex2f(s[j][1]);
            s[j][2] = ex2f(s[j][2]); s[j][3] = ex2f(s[j][3]);
        }

        // O += P @ V and l += P @ ones : 7 key-windows x 7 n-subtiles
        #pragma unroll
        for (int ww = 0; ww < 7; ww++) {
            uint32_t a[4];
            a[0] = packh2(s[2*ww][0],   s[2*ww][1]);     // row gid,  klo pair
            a[1] = packh2(s[2*ww][2],   s[2*ww][3]);     // row gid+8, klo
            a[2] = packh2(s[2*ww+1][0], s[2*ww+1][1]);   // row gid,  khi
            a[3] = packh2(s[2*ww+1][2], s[2*ww+1][3]);   // row gid+8, khi
            #pragma unroll
            for (int n = 0; n < 7; n++) {
                const uint2 bb = *(const uint2*)&Vst[buf][n * 8 + gid][ww * 8 + 2 * t4];
                uint32_t bfr[2] = { bb.x, bb.y };
                mma_f16(oacc[n], a, bfr);
            }
        }
        buf ^= 1;
    }

    // l sits in col 48 -> t4==0 lanes; broadcast within quad
    const int lsrc = lane & ~3;
    const float l0 = __shfl_sync(0xffffffffu, oacc[6][0], lsrc);
    const float l1 = __shfl_sync(0xffffffffu, oacc[6][2], lsrc);

    const int b = bh >> 3, head = bh & 7;
    const int q0r = qbase + w * 16 + gid;
    const float inv0 = 1.f / l0;
    const float inv1 = 1.f / l1;
    float* od0 = o_out + ((size_t)b * NP + q0r) * C + head * HD;
    float* od1 = od0 + (size_t)8 * C;
    #pragma unroll
    for (int n = 0; n < 6; n++) {
        const int col = n * 8 + 2 * t4;
        float2 r0; r0.x = oacc[n][0] * inv0; r0.y = oacc[n][1] * inv0;
        float2 r1; r1.x = oacc[n][2] * inv1; r1.y = oacc[n][3] * inv1;
        *(float2*)(od0 + col) = r0;
        *(float2*)(od1 + col) = r1;
    }
}

// =====================================================================
// Kernel 3: upsample + bias + LN, 2x2 quad per block.
// Writes fp16 y in PERM16 channel order.
// =====================================================================
__global__ __launch_bounds__(128) void up_ln_kernel(
    const float* __restrict__ lp_w, const float* __restrict__ lp_b,
    const float* __restrict__ ln_w, const float* __restrict__ ln_b)
{
    const int pp0 = blockIdx.x;
    const int b   = pp0 / NP;
    const int p2  = pp0 - b * NP;
    const int hh  = p2 / PW;
    const int ww  = p2 - hh * PW;
    const float* orow = g_o + (size_t)pp0 * C;

    const int tid = threadIdx.x;
    float ov[3], lb[3], lw[3], lnbv[3];
    float4 w4[3];
    int cperm[3];
    #pragma unroll
    for (int r = 0; r < 3; r++) {
        const int c = tid + r * 128;
        ov[r] = orow[c];
        w4[r] = *(const float4*)(lp_w + c * 4);
        lb[r] = lp_b[c];
        lw[r] = ln_w[c];
        lnbv[r] = ln_b[c];
        cperm[r] = (c & ~15) | perm16(c & 15);
    }

    float s[4] = {}, s2[4] = {};
    #pragma unroll
    for (int r = 0; r < 3; r++) {
        const float v0 = ov[r] * w4[r].x + lb[r];
        const float v1 = ov[r] * w4[r].y + lb[r];
        const float v2 = ov[r] * w4[r].z + lb[r];
        const float v3 = ov[r] * w4[r].w + lb[r];
        s[0] += v0; s2[0] += v0 * v0;
        s[1] += v1; s2[1] += v1 * v1;
        s[2] += v2; s2[2] += v2 * v2;
        s[3] += v3; s2[3] += v3 * v3;
    }

    __shared__ float rs[4][4], rs2[4][4];
    #pragma unroll
    for (int pq = 0; pq < 4; pq++) {
        float a = s[pq], a2 = s2[pq];
        #pragma unroll
        for (int off = 16; off > 0; off >>= 1) {
            a  += __shfl_down_sync(0xffffffffu, a,  off);
            a2 += __shfl_down_sync(0xffffffffu, a2, off);
        }
        if ((tid & 31) == 0) { rs[tid >> 5][pq] = a; rs2[tid >> 5][pq] = a2; }
    }
    __syncthreads();

    float mean[4], inv[4];
    #pragma unroll
    for (int pq = 0; pq < 4; pq++) {
        const float S  = rs[0][pq] + rs[1][pq] + rs[2][pq] + rs[3][pq];
        const float S2 = rs2[0][pq] + rs2[1][pq] + rs2[2][pq] + rs2[3][pq];
        mean[pq] = S * (1.f / C);
        const float var = S2 * (1.f / C) - mean[pq] * mean[pq];
        inv[pq] = rsqrtf(var + EPS);
    }

    #pragma unroll
    for (int pq = 0; pq < 4; pq++) {
        const int pp = pq >> 1, qq = pq & 1;
        __half* yrow = g_y + ((size_t)b * NPIX + (2 * hh + pp) * WW + (2 * ww + qq)) * C;
        #pragma unroll
        for (int r = 0; r < 3; r++) {
            const float wsel = (pq == 0) ? w4[r].x : (pq == 1) ? w4[r].y
                              : (pq == 2) ? w4[r].z : w4[r].w;
            const float val = ov[r] * wsel + lb[r];
            yrow[cperm[r]] = __float2half((val - mean[pq]) * inv[pq] * lw[r] + lnbv[r]);
        }
    }
}

// =====================================================================
// launcher
// =====================================================================
extern "C" void kernel_launch(void* const* d_in, const int* in_sizes, int n_in,
                              void* d_out, int out_size)
{
    const float* x      = (const float*)d_in[0];
    const float* qkv_w  = (const float*)d_in[1];
    const float* qkv_b  = (const float*)d_in[2];
    const float* proj_w = (const float*)d_in[3];
    const float* proj_b = (const float*)d_in[4];
    const float* lp_w   = (const float*)d_in[5];
    const float* lp_b   = (const float*)d_in[6];
    const float* ln_w   = (const float*)d_in[7];
    const float* ln_b   = (const float*)d_in[8];
    float* out = (float*)d_out;

    float* o_ptr = nullptr;
    cudaGetSymbolAddress((void**)&o_ptr, g_o);

    // 0) prep (16-channel groups)
    {
        const int total = PG1 + PG2 + PG3;
        prep_kernel<<<(total + 255) / 256, 256>>>(x, qkv_w, proj_w);
    }
    // 1) QKV gemm (fp16)
    {
        dim3 grid((3 * C) / 128, (BATCH * NP) / 128);
        qkv_gemm_f16<<<grid, 256>>>(qkv_b);
    }
    // 2) attention (fp16)
    {
        dim3 grid(NP / QB, BH);
        attn_mma<<<grid, ATH>>>(o_ptr);
    }
    // 3) upsample + LN
    {
        up_ln_kernel<<<BATCH * NP, 128>>>(lp_w, lp_b, ln_w, ln_b);
    }
    // 4) proj gemm (fp16)
    {
        dim3 grid(C / 128, (BATCH * NPIX) / 128);
        proj_gemm_f16<<<grid, 256>>>(proj_b, out);
    }
}